// round 7
// baseline (speedup 1.0000x reference)
#include <cuda_runtime.h>
#include <math.h>
#include <cstdint>

#define BATCH 256
#define NA    32
#define OBS   128
#define ACT   8
#define DV    128
#define DH    64
#define DO    8
#define S1    132   // padded stride (floats) for 128-wide rows, float4-aligned
#define S2    68    // padded stride for 64-wide rows

// ---- SMEM layout (floats) ----
#define OFF_STATES 0
#define OFF_T      (OFF_STATES + NA*S1)
#define OFF_AVA    (OFF_T + NA*S1)
#define OFF_DIFF   (OFF_AVA + NA*S1)
#define OFF_W      (OFF_DIFF + NA*S1)
#define OFF_AW1    (OFF_W + NA*NA)
#define OFF_DW1    (OFF_AW1 + NA*S2)
#define OFF_BW1    (OFF_DW1 + NA*S2)
#define OFF_ACT    (OFF_BW1 + NA*S2)
#define OFF_POL    (OFF_ACT + NA*ACT)
#define OFF_W2     (OFF_POL + NA*ACT)
#define OFF_STAGE  (OFF_W2 + DH*DO)        // [2 buf][8 warps][8 rows][16 floats]
#define SMEM_FLOATS (OFF_STAGE + 2*8*8*16)
#define SMEM_BYTES  (SMEM_FLOATS * 4)

__device__ float g_M[OBS * OBS];   // (Wq @ Wk^T) / sqrt(DK), contract over DK

__device__ __forceinline__ void cp_async16(unsigned int saddr, const void* gptr) {
    asm volatile("cp.async.ca.shared.global [%0], [%1], 16;"
                 :: "r"(saddr), "l"(gptr));
}
__device__ __forceinline__ void cp_commit() {
    asm volatile("cp.async.commit_group;");
}
__device__ __forceinline__ void cp_wait1() {
    asm volatile("cp.async.wait_group 1;");
}

// ---------------------------------------------------------------------------
// M[i][j] = (sum_d Wq[i][d] * Wk[j][d]) / sqrt(128)
// ---------------------------------------------------------------------------
__global__ void compute_M_kernel(const float* __restrict__ Wq,
                                 const float* __restrict__ Wk) {
    __shared__ float qs[16][OBS + 4];
    __shared__ float ks[16][OBS + 4];
    const int i0 = (blockIdx.x & 7) * 16;
    const int j0 = (blockIdx.x >> 3) * 16;
    const int tid = threadIdx.x;
    for (int idx = tid; idx < 16 * 32; idx += 256) {
        int r = idx >> 5, d4 = (idx & 31) * 4;
        *reinterpret_cast<float4*>(&qs[r][d4]) =
            *reinterpret_cast<const float4*>(&Wq[(i0 + r) * OBS + d4]);
        *reinterpret_cast<float4*>(&ks[r][d4]) =
            *reinterpret_cast<const float4*>(&Wk[(j0 + r) * OBS + d4]);
    }
    __syncthreads();
    const int ti = tid >> 4, tj = tid & 15;
    float acc = 0.f;
    #pragma unroll 8
    for (int d = 0; d < OBS; ++d)
        acc = fmaf(qs[ti][d], ks[tj][d], acc);
    g_M[(i0 + ti) * OBS + j0 + tj] = acc * 0.08838834764831845f;
}

// ---------------------------------------------------------------------------
// Main fused kernel: one CTA per batch element, 256 threads
// ---------------------------------------------------------------------------
__global__ __launch_bounds__(256, 2)
void critic_kernel(const float* __restrict__ states,
                   const float* __restrict__ policies,
                   const float* __restrict__ actions,
                   const float* __restrict__ Wv,
                   const float* __restrict__ W1,
                   const float* __restrict__ W2,
                   float* __restrict__ value_out,
                   float* __restrict__ weight_out)
{
    extern __shared__ float sm[];
    float* s_states = sm + OFF_STATES;
    float* s_t      = sm + OFF_T;
    float* s_avA    = sm + OFF_AVA;
    float* s_diff   = sm + OFF_DIFF;
    float* s_w      = sm + OFF_W;
    float* s_aW1    = sm + OFF_AW1;
    float* s_dW1    = sm + OFF_DW1;
    float* s_bW1    = sm + OFF_BW1;
    float* s_act    = sm + OFF_ACT;
    float* s_pol    = sm + OFF_POL;
    float* s_W2     = sm + OFF_W2;
    float* s_stage  = sm + OFF_STAGE;

    const int b   = blockIdx.x;
    const int tid = threadIdx.x;

    // ---- stage inputs ----
    {
        const float* st_b = states + (size_t)b * NA * OBS;
        for (int idx = tid; idx < NA * OBS / 4; idx += 256) {
            int i = idx >> 5, d4 = (idx & 31) * 4;
            *reinterpret_cast<float4*>(&s_states[i * S1 + d4]) =
                *reinterpret_cast<const float4*>(&st_b[i * OBS + d4]);
        }
        for (int idx = tid; idx < NA * ACT; idx += 256) {
            s_act[idx] = actions [(size_t)b * NA * ACT + idx];
            s_pol[idx] = policies[(size_t)b * NA * ACT + idx];
        }
        for (int idx = tid; idx < DH * DO; idx += 256) s_W2[idx] = W2[idx];
    }
    __syncthreads();

    // =========================================================================
    // Phase 1: t = states@M and avA/diff = tanh(concat@Wv).
    // Warp w owns cols [16w,16w+16). Per-warp cp.async double-buffered staging
    // of the next 4-row M/Wv chunk hides the ~234cyc L2 latency. No CTA
    // barriers: cp.async.wait_group + __syncwarp is warp-scope complete.
    // =========================================================================
    {
        const int w   = tid >> 5;
        const int l   = tid & 31;
        const int g   = l >> 2;
        const int cg4 = (l & 3) * 4;
        const int c0  = w * 16 + cg4;

        // lane's staging slot: row = l>>2 (0..3 => M, 4..7 => Wv), colgrp = l&3
        const int srow = l >> 2;
        const int scg  = l & 3;
        float* warp_stage = s_stage + w * (8 * 16);          // [8][16] per warp
        const int buf_stride = 8 * 8 * 16;                    // floats per buffer
        unsigned int stage_waddr = (unsigned int)__cvta_generic_to_shared(
            warp_stage + srow * 16 + scg * 4);

        // prefetch chunk for kk into buffer p (lane-parallel, 16B each)
        auto prefetch = [&](int p, int kk) {
            const float* src = (srow < 4)
                ? &g_M[(kk + srow) * OBS + w * 16 + scg * 4]
                : &Wv [(kk + srow - 4) * DV + w * 16 + scg * 4];
            cp_async16(stage_waddr + p * buf_stride * 4, src);
            cp_commit();
        };

        prefetch(0, 0);

        float4 tAcc[4], vAcc[4];
        #pragma unroll
        for (int m = 0; m < 4; ++m) {
            tAcc[m] = make_float4(0.f, 0.f, 0.f, 0.f);
            vAcc[m] = make_float4(0.f, 0.f, 0.f, 0.f);
        }

        int buf = 0;
        for (int kk = 0; kk < OBS; kk += 4) {
            if (kk + 4 < OBS) prefetch(buf ^ 1, kk + 4);
            else              cp_commit();      // keep group count symmetric
            cp_wait1();                          // current chunk resident
            __syncwarp();

            const float* stg = warp_stage + buf * buf_stride;

            float4 sv[4];
            #pragma unroll
            for (int m = 0; m < 4; ++m)
                sv[m] = *reinterpret_cast<const float4*>(&s_states[(g + 8 * m) * S1 + kk]);
            #pragma unroll
            for (int t = 0; t < 4; ++t) {
                float4 mq = *reinterpret_cast<const float4*>(&stg[ t      * 16 + cg4]);
                float4 wv = *reinterpret_cast<const float4*>(&stg[(t + 4) * 16 + cg4]);
                #pragma unroll
                for (int m = 0; m < 4; ++m) {
                    float s = reinterpret_cast<const float*>(&sv[m])[t];
                    tAcc[m].x = fmaf(s, mq.x, tAcc[m].x);
                    tAcc[m].y = fmaf(s, mq.y, tAcc[m].y);
                    tAcc[m].z = fmaf(s, mq.z, tAcc[m].z);
                    tAcc[m].w = fmaf(s, mq.w, tAcc[m].w);
                    vAcc[m].x = fmaf(s, wv.x, vAcc[m].x);
                    vAcc[m].y = fmaf(s, wv.y, vAcc[m].y);
                    vAcc[m].z = fmaf(s, wv.z, vAcc[m].z);
                    vAcc[m].w = fmaf(s, wv.w, vAcc[m].w);
                }
            }
            __syncwarp();        // all lanes done reading before overwrite
            buf ^= 1;
        }
        #pragma unroll
        for (int m = 0; m < 4; ++m)
            *reinterpret_cast<float4*>(&s_t[(g + 8 * m) * S1 + c0]) = tAcc[m];

        // action/policy tail (8 extra K) on the shared states partial
        float4 accA[4], accP[4];
        #pragma unroll
        for (int m = 0; m < 4; ++m) { accA[m] = vAcc[m]; accP[m] = vAcc[m]; }
        #pragma unroll
        for (int kk = 0; kk < ACT; ++kk) {
            float4 wv = *reinterpret_cast<const float4*>(&Wv[(OBS + kk) * DV + c0]);
            #pragma unroll
            for (int m = 0; m < 4; ++m) {
                float a = s_act[(g + 8 * m) * ACT + kk];
                float p = s_pol[(g + 8 * m) * ACT + kk];
                accA[m].x = fmaf(a, wv.x, accA[m].x);
                accA[m].y = fmaf(a, wv.y, accA[m].y);
                accA[m].z = fmaf(a, wv.z, accA[m].z);
                accA[m].w = fmaf(a, wv.w, accA[m].w);
                accP[m].x = fmaf(p, wv.x, accP[m].x);
                accP[m].y = fmaf(p, wv.y, accP[m].y);
                accP[m].z = fmaf(p, wv.z, accP[m].z);
                accP[m].w = fmaf(p, wv.w, accP[m].w);
            }
        }
        #pragma unroll
        for (int m = 0; m < 4; ++m) {
            float4 tA, dF;
            tA.x = tanhf(accA[m].x); tA.y = tanhf(accA[m].y);
            tA.z = tanhf(accA[m].z); tA.w = tanhf(accA[m].w);
            dF.x = tanhf(accP[m].x) - tA.x; dF.y = tanhf(accP[m].y) - tA.y;
            dF.z = tanhf(accP[m].z) - tA.z; dF.w = tanhf(accP[m].w) - tA.w;
            *reinterpret_cast<float4*>(&s_avA [(g + 8 * m) * S1 + c0]) = tA;
            *reinterpret_cast<float4*>(&s_diff[(g + 8 * m) * S1 + c0]) = dF;
        }
    }
    __syncthreads();

    // =========================================================================
    // Phase 2a: score[i][j] = t[i,:] . states[j,:]  (scale folded into M).
    // Warp w produces rows 4w..4w+3 entirely locally.
    // =========================================================================
    {
        const int i0 = (tid >> 4) * 2;
        const int j0 = (tid & 15) * 2;
        float a00 = 0.f, a01 = 0.f, a10 = 0.f, a11 = 0.f;
        for (int kk = 0; kk < OBS; kk += 4) {
            float4 q0 = *reinterpret_cast<const float4*>(&s_t[ i0      * S1 + kk]);
            float4 q1 = *reinterpret_cast<const float4*>(&s_t[(i0 + 1) * S1 + kk]);
            float4 k0 = *reinterpret_cast<const float4*>(&s_states[ j0      * S1 + kk]);
            float4 k1 = *reinterpret_cast<const float4*>(&s_states[(j0 + 1) * S1 + kk]);
            a00 = fmaf(q0.x, k0.x, fmaf(q0.y, k0.y, fmaf(q0.z, k0.z, fmaf(q0.w, k0.w, a00))));
            a01 = fmaf(q0.x, k1.x, fmaf(q0.y, k1.y, fmaf(q0.z, k1.z, fmaf(q0.w, k1.w, a01))));
            a10 = fmaf(q1.x, k0.x, fmaf(q1.y, k0.y, fmaf(q1.z, k0.z, fmaf(q1.w, k0.w, a10))));
            a11 = fmaf(q1.x, k1.x, fmaf(q1.y, k1.y, fmaf(q1.z, k1.z, fmaf(q1.w, k1.w, a11))));
        }
        s_w[i0 * NA + j0]           = a00;
        s_w[i0 * NA + j0 + 1]       = a01;
        s_w[(i0 + 1) * NA + j0]     = a10;
        s_w[(i0 + 1) * NA + j0 + 1] = a11;
    }
    __syncwarp();

    // =========================================================================
    // Phase 2a': softmax — warp w owns rows 4w..4w+3 (warp-local sync only)
    // =========================================================================
    {
        const int warp = tid >> 5, lane = tid & 31;
        #pragma unroll
        for (int rr = 0; rr < 4; ++rr) {
            const int row = warp * 4 + rr;
            float v = s_w[row * NA + lane];
            float m = v;
            #pragma unroll
            for (int off = 16; off > 0; off >>= 1)
                m = fmaxf(m, __shfl_xor_sync(0xffffffffu, m, off));
            float e = expf(v - m);
            float s = e;
            #pragma unroll
            for (int off = 16; off > 0; off >>= 1)
                s += __shfl_xor_sync(0xffffffffu, s, off);
            float w = e / s;
            s_w[row * NA + lane] = w;
            weight_out[(size_t)b * NA * NA + row * NA + lane] = w;
        }
    }

    // =========================================================================
    // Phase 2b: aW1 = avA@W1, dW1 = diff@W1. 2 j-rows x 4 h per thread.
    // =========================================================================
    {
        const int j0 = (tid >> 4) * 2;
        const int h0 = (tid & 15) * 4;
        float4 aA0 = make_float4(0,0,0,0), aA1 = make_float4(0,0,0,0);
        float4 aD0 = make_float4(0,0,0,0), aD1 = make_float4(0,0,0,0);
        for (int d = 0; d < DV; d += 4) {
            float4 av0 = *reinterpret_cast<const float4*>(&s_avA [ j0      * S1 + d]);
            float4 av1 = *reinterpret_cast<const float4*>(&s_avA [(j0 + 1) * S1 + d]);
            float4 df0 = *reinterpret_cast<const float4*>(&s_diff[ j0      * S1 + d]);
            float4 df1 = *reinterpret_cast<const float4*>(&s_diff[(j0 + 1) * S1 + d]);
            #pragma unroll
            for (int t = 0; t < 4; ++t) {
                float4 w1 = *reinterpret_cast<const float4*>(&W1[(d + t) * DH + h0]);
                float a0 = reinterpret_cast<const float*>(&av0)[t];
                float a1 = reinterpret_cast<const float*>(&av1)[t];
                float d0 = reinterpret_cast<const float*>(&df0)[t];
                float d1 = reinterpret_cast<const float*>(&df1)[t];
                aA0.x = fmaf(a0, w1.x, aA0.x); aA0.y = fmaf(a0, w1.y, aA0.y);
                aA0.z = fmaf(a0, w1.z, aA0.z); aA0.w = fmaf(a0, w1.w, aA0.w);
                aA1.x = fmaf(a1, w1.x, aA1.x); aA1.y = fmaf(a1, w1.y, aA1.y);
                aA1.z = fmaf(a1, w1.z, aA1.z); aA1.w = fmaf(a1, w1.w, aA1.w);
                aD0.x = fmaf(d0, w1.x, aD0.x); aD0.y = fmaf(d0, w1.y, aD0.y);
                aD0.z = fmaf(d0, w1.z, aD0.z); aD0.w = fmaf(d0, w1.w, aD0.w);
                aD1.x = fmaf(d1, w1.x, aD1.x); aD1.y = fmaf(d1, w1.y, aD1.y);
                aD1.z = fmaf(d1, w1.z, aD1.z); aD1.w = fmaf(d1, w1.w, aD1.w);
            }
        }
        *reinterpret_cast<float4*>(&s_aW1[ j0      * S2 + h0]) = aA0;
        *reinterpret_cast<float4*>(&s_aW1[(j0 + 1) * S2 + h0]) = aA1;
        *reinterpret_cast<float4*>(&s_dW1[ j0      * S2 + h0]) = aD0;
        *reinterpret_cast<float4*>(&s_dW1[(j0 + 1) * S2 + h0]) = aD1;
    }
    __syncthreads();

    // =========================================================================
    // Phase 4: bW1 = w @ aW1   [32 x 64]
    // =========================================================================
    {
        const int a0 = (tid >> 4) * 2;
        const int h0 = (tid & 15) * 4;
        float4 acc0 = make_float4(0,0,0,0), acc1 = make_float4(0,0,0,0);
        for (int j = 0; j < NA; j += 4) {
            float4 w0 = *reinterpret_cast<const float4*>(&s_w[ a0      * NA + j]);
            float4 w1 = *reinterpret_cast<const float4*>(&s_w[(a0 + 1) * NA + j]);
            #pragma unroll
            for (int t = 0; t < 4; ++t) {
                float4 aw = *reinterpret_cast<const float4*>(&s_aW1[(j + t) * S2 + h0]);
                float v0 = reinterpret_cast<const float*>(&w0)[t];
                float v1 = reinterpret_cast<const float*>(&w1)[t];
                acc0.x = fmaf(v0, aw.x, acc0.x); acc0.y = fmaf(v0, aw.y, acc0.y);
                acc0.z = fmaf(v0, aw.z, acc0.z); acc0.w = fmaf(v0, aw.w, acc0.w);
                acc1.x = fmaf(v1, aw.x, acc1.x); acc1.y = fmaf(v1, aw.y, acc1.y);
                acc1.z = fmaf(v1, aw.z, acc1.z); acc1.w = fmaf(v1, aw.w, acc1.w);
            }
        }
        *reinterpret_cast<float4*>(&s_bW1[ a0      * S2 + h0]) = acc0;
        *reinterpret_cast<float4*>(&s_bW1[(a0 + 1) * S2 + h0]) = acc1;
    }
    __syncthreads();

    // =========================================================================
    // Phase 5: per (a,c): h = leaky(bW1[a] + w*dW1[c]); out = h @ W2.
    // 4 a-values per thread so dW1/W2 loads amortize.
    // =========================================================================
    {
        const int a0 = tid >> 5;      // 0..7
        const int c  = tid & 31;      // 0..31
        float wk[4];
        #pragma unroll
        for (int k = 0; k < 4; ++k) wk[k] = s_w[(a0 + 8 * k) * NA + c];

        float4 accL[4], accH[4];
        #pragma unroll
        for (int k = 0; k < 4; ++k) {
            accL[k] = make_float4(0,0,0,0);
            accH[k] = make_float4(0,0,0,0);
        }
        for (int h = 0; h < DH; h += 4) {
            float4 dq = *reinterpret_cast<const float4*>(&s_dW1[c * S2 + h]);
            float4 w2lo[4], w2hi[4];
            #pragma unroll
            for (int t = 0; t < 4; ++t) {
                w2lo[t] = *reinterpret_cast<const float4*>(&s_W2[(h + t) * DO]);
                w2hi[t] = *reinterpret_cast<const float4*>(&s_W2[(h + t) * DO + 4]);
            }
            #pragma unroll
            for (int k = 0; k < 4; ++k) {
                float4 bq = *reinterpret_cast<const float4*>(&s_bW1[(a0 + 8 * k) * S2 + h]);
                #pragma unroll
                for (int t = 0; t < 4; ++t) {
                    float x = fmaf(wk[k],
                                   reinterpret_cast<const float*>(&dq)[t],
                                   reinterpret_cast<const float*>(&bq)[t]);
                    x = fmaxf(x, 0.01f * x);   // leaky_relu(0.01)
                    accL[k].x = fmaf(x, w2lo[t].x, accL[k].x);
                    accL[k].y = fmaf(x, w2lo[t].y, accL[k].y);
                    accL[k].z = fmaf(x, w2lo[t].z, accL[k].z);
                    accL[k].w = fmaf(x, w2lo[t].w, accL[k].w);
                    accH[k].x = fmaf(x, w2hi[t].x, accH[k].x);
                    accH[k].y = fmaf(x, w2hi[t].y, accH[k].y);
                    accH[k].z = fmaf(x, w2hi[t].z, accH[k].z);
                    accH[k].w = fmaf(x, w2hi[t].w, accH[k].w);
                }
            }
        }
        #pragma unroll
        for (int k = 0; k < 4; ++k) {
            float4* outp = reinterpret_cast<float4*>(
                value_out + (((size_t)b * NA + (a0 + 8 * k)) * NA + c) * DO);
            outp[0] = accL[k];
            outp[1] = accH[k];
        }
    }
}

extern "C" void kernel_launch(void* const* d_in, const int* in_sizes, int n_in,
                              void* d_out, int out_size) {
    const float* states   = (const float*)d_in[0];
    const float* policies = (const float*)d_in[1];
    const float* actions  = (const float*)d_in[2];
    const float* Wk       = (const float*)d_in[3];
    const float* Wq       = (const float*)d_in[4];
    const float* Wv       = (const float*)d_in[5];
    const float* W1       = (const float*)d_in[6];
    const float* W2       = (const float*)d_in[7];

    float* value_out  = (float*)d_out;                              // [B,N,N,8]
    float* weight_out = value_out + (size_t)BATCH * NA * NA * DO;   // [B,N,N]

    compute_M_kernel<<<64, 256>>>(Wq, Wk);

    cudaFuncSetAttribute(critic_kernel,
                         cudaFuncAttributeMaxDynamicSharedMemorySize, SMEM_BYTES);
    critic_kernel<<<BATCH, 256, SMEM_BYTES>>>(
        states, policies, actions, Wv, W1, W2, value_out, weight_out);
}